// round 2
// baseline (speedup 1.0000x reference)
#include <cuda_runtime.h>
#include <cstdint>

#define BB 512
#define TT 64
#define II 64
#define HH 128
#define H3 384
#define SH 129   // padded row stride for 128-wide smem tiles
#define SA 129   // padded row stride for post-kernel 128-wide tiles

// ---------------------------------------------------------------------------
// helpers
// ---------------------------------------------------------------------------
__device__ __forceinline__ float fast_sigmoid(float v) {
    return __fdividef(1.0f, 1.0f + __expf(-v));
}
__device__ __forceinline__ float fast_tanh(float v) {
    return __fdividef(2.0f, 1.0f + __expf(-2.0f * v)) - 1.0f;
}

// Stage a [128][128] row-major weight block (W[g][k]) into smem s_w[g*SH + k].
__device__ __forceinline__ void stage_w(const float* __restrict__ W,
                                        float* __restrict__ s_w, int tid) {
    const float4* src = (const float4*)W;
#pragma unroll
    for (int it = 0; it < 16; it++) {
        int l = tid + it * 256;        // 0..4095 float4s
        int g = l >> 5;                // row (32 float4 per row)
        int k = (l & 31) << 2;         // col
        float4 v = src[l];
        float* d = s_w + g * SH + k;
        d[0] = v.x; d[1] = v.y; d[2] = v.z; d[3] = v.w;
    }
}

// C[128][128] = s_h[128rows][128k] * s_w[128cols][128k]^T  (both k-padded SH)
// thread tile 8x8 (rows ty4,ty4+64.., cols tx4,tx4+64..)
__device__ __forceinline__ void gemm128(const float* __restrict__ s_h,
                                        const float* __restrict__ s_w,
                                        int ty4, int tx4, float acc[8][8]) {
#pragma unroll
    for (int ii = 0; ii < 8; ii++)
#pragma unroll
        for (int jj = 0; jj < 8; jj++) acc[ii][jj] = 0.0f;

#pragma unroll 4
    for (int k = 0; k < 128; k++) {
        float a[8], b[8];
#pragma unroll
        for (int u = 0; u < 4; u++) {
            a[u]     = s_h[(ty4 + u) * SH + k];
            a[u + 4] = s_h[(ty4 + 64 + u) * SH + k];
            b[u]     = s_w[(tx4 + u) * SH + k];
            b[u + 4] = s_w[(tx4 + 64 + u) * SH + k];
        }
#pragma unroll
        for (int ii = 0; ii < 8; ii++)
#pragma unroll
            for (int jj = 0; jj < 8; jj++)
                acc[ii][jj] = fmaf(a[ii], b[jj], acc[ii][jj]);
    }
}

// ---------------------------------------------------------------------------
// GRU kernel: grid (I=64 features, 4 b-chunks of 128), 256 threads.
// h state [128][128] resident in smem across all T steps.
// Fuses the final fp_w projection; writes ht [B,I,H] into d_out's ht region.
// ---------------------------------------------------------------------------
#define GRU_SMEM_FLOATS (128 * SH + 128 * SH + 256 + 3 * 384)

extern "C" __global__ void __launch_bounds__(256, 1)
gru_kernel(const float* __restrict__ x,      // [B,T,I]
           const float* __restrict__ W_ih,   // [I,3H]
           const float* __restrict__ W_hh,   // [I,3H,H]
           const float* __restrict__ b_ih,   // [I,3H]
           const float* __restrict__ b_hh,   // [I,3H]
           const float* __restrict__ fp_w,   // [H,H]
           const float* __restrict__ fp_b,   // [H]
           float* __restrict__ ht_out)       // [B,I,H]
{
    const int i_feat = blockIdx.x;
    const int b0 = blockIdx.y << 7;
    const int tid = threadIdx.x;
    const int tx4 = (tid & 15) << 2;
    const int ty4 = (tid >> 4) << 2;

    extern __shared__ float sm[];
    float* s_h   = sm;                       // [128][SH]
    float* s_w   = s_h + 128 * SH;           // [128][SH]
    float* s_x   = s_w + 128 * SH;           // [2][128] double-buffered x column
    float* s_wih = s_x + 256;                // [384]
    float* s_bih = s_wih + 384;              // [384]
    float* s_bhh = s_bih + 384;              // [384]

    for (int l = tid; l < 128 * SH; l += 256) s_h[l] = 0.0f;
    for (int l = tid; l < 384; l += 256) {
        s_wih[l] = W_ih[i_feat * H3 + l];
        s_bih[l] = b_ih[i_feat * H3 + l];
        s_bhh[l] = b_hh[i_feat * H3 + l];
    }
    if (tid < 128)  // x for t=0
        s_x[tid] = x[(size_t)(b0 + tid) * (TT * II) + i_feat];

    const float* Wb = W_hh + (size_t)i_feat * H3 * HH;

    int rr[8], cc[8];
#pragma unroll
    for (int u = 0; u < 4; u++) {
        rr[u] = ty4 + u;       rr[u + 4] = ty4 + 64 + u;
        cc[u] = tx4 + u;       cc[u + 4] = tx4 + 64 + u;
    }

    float gate[8][8];   // r, then overwritten by ncand
    float acc[8][8];

    for (int t = 0; t < TT; t++) {
        const float* sx = s_x + ((t & 1) << 7);

        // ---- gate r (rows 0..127 of W_hh[i]) ----
        stage_w(Wb, s_w, tid);
        __syncthreads();
        gemm128(s_h, s_w, ty4, tx4, acc);
#pragma unroll
        for (int ii = 0; ii < 8; ii++) {
            float xr = sx[rr[ii]];
#pragma unroll
            for (int jj = 0; jj < 8; jj++) {
                int g = cc[jj];
                float pre = acc[ii][jj] + s_bhh[g] + xr * s_wih[g] + s_bih[g];
                gate[ii][jj] = fast_sigmoid(pre);
            }
        }
        __syncthreads();

        // ---- gate n (rows 256..383) : ncand = tanh(gi_n + r*(Whh_n h + bhh_n)) ----
        stage_w(Wb + 256 * 128, s_w, tid);
        __syncthreads();
        gemm128(s_h, s_w, ty4, tx4, acc);
#pragma unroll
        for (int ii = 0; ii < 8; ii++) {
            float xr = sx[rr[ii]];
#pragma unroll
            for (int jj = 0; jj < 8; jj++) {
                int g = 256 + cc[jj];
                float pre = xr * s_wih[g] + s_bih[g] +
                            gate[ii][jj] * (acc[ii][jj] + s_bhh[g]);
                gate[ii][jj] = fast_tanh(pre);   // now holds ncand
            }
        }
        __syncthreads();

        // ---- gate z (rows 128..255), prefetch x(t+1) ----
        stage_w(Wb + 128 * 128, s_w, tid);
        if (tid < 128 && (t + 1) < TT)
            s_x[(((t + 1) & 1) << 7) + tid] =
                x[(size_t)(b0 + tid) * (TT * II) + (t + 1) * II + i_feat];
        __syncthreads();
        gemm128(s_h, s_w, ty4, tx4, acc);
        __syncthreads();   // everyone done reading s_h before updates

#pragma unroll
        for (int ii = 0; ii < 8; ii++) {
            float xr = sx[rr[ii]];
#pragma unroll
            for (int jj = 0; jj < 8; jj++) {
                int g = 128 + cc[jj];
                float z = fast_sigmoid(acc[ii][jj] + s_bhh[g] + xr * s_wih[g] + s_bih[g]);
                int idx = rr[ii] * SH + cc[jj];
                float ho = s_h[idx];
                s_h[idx] = (1.0f - z) * gate[ii][jj] + z * ho;
            }
        }
        // no trailing sync needed: next iteration syncs after staging s_w
        __syncthreads();
    }

    // ---- ht = fp_w * h + fp_b, write to global ----
    stage_w(fp_w, s_w, tid);
    if (tid < 128) s_wih[tid] = fp_b[tid];   // reuse (dead after loop)
    __syncthreads();
    gemm128(s_h, s_w, ty4, tx4, acc);

#pragma unroll
    for (int ii = 0; ii < 8; ii++) {
        int r = rr[ii];
        size_t base = ((size_t)(b0 + r) * II + i_feat) * HH;
        float4 v0 = make_float4(acc[ii][0] + s_wih[tx4 + 0],
                                acc[ii][1] + s_wih[tx4 + 1],
                                acc[ii][2] + s_wih[tx4 + 2],
                                acc[ii][3] + s_wih[tx4 + 3]);
        float4 v1 = make_float4(acc[ii][4] + s_wih[64 + tx4 + 0],
                                acc[ii][5] + s_wih[64 + tx4 + 1],
                                acc[ii][6] + s_wih[64 + tx4 + 2],
                                acc[ii][7] + s_wih[64 + tx4 + 3]);
        *(float4*)(ht_out + base + tx4)      = v0;
        *(float4*)(ht_out + base + 64 + tx4) = v1;
    }
}

// ---------------------------------------------------------------------------
// Post kernel: one block per batch row b, 256 threads.
// graph conv hop1 + hop2, then mul-attention + output head.
// ---------------------------------------------------------------------------
#define POST_SMEM_FLOATS (64 * SA + 64 * SA + 64 * 64 + 128 * SH + 128 + 128 + 128 + 128 + 64 + 32)

__device__ __forceinline__ void adjmm(const float* __restrict__ s_adj,
                                      const float* __restrict__ src,
                                      float* __restrict__ dst, int h, int i0) {
    for (int m = 0; m < 32; m++) {
        int i = i0 + m;
        float a = 0.0f;
#pragma unroll 8
        for (int j = 0; j < 64; j++)
            a = fmaf(s_adj[i * 64 + j], src[j * SA + h], a);
        dst[i * SA + h] = a;
    }
}

__device__ __forceinline__ void lin128(const float* __restrict__ s_w,
                                       const float* __restrict__ s_b,
                                       const float* __restrict__ src,
                                       float* __restrict__ dst,
                                       int h, int i0, bool do_relu) {
    float acc[32];
#pragma unroll
    for (int m = 0; m < 32; m++) acc[m] = 0.0f;
    for (int k = 0; k < 128; k++) {
        float w = s_w[h * SH + k];
#pragma unroll 8
        for (int m = 0; m < 32; m++)
            acc[m] = fmaf(w, src[(i0 + m) * SA + k], acc[m]);
    }
    float bb = s_b[h];
#pragma unroll
    for (int m = 0; m < 32; m++) {
        float v = acc[m] + bb;
        dst[(i0 + m) * SA + h] = do_relu ? fmaxf(v, 0.0f) : v;
    }
}

extern "C" __global__ void __launch_bounds__(256, 1)
post_kernel(const float* __restrict__ ht,     // [B,I,H]
            const float* __restrict__ adj,    // [I,I]
            const float* __restrict__ g1_w, const float* __restrict__ g1_b,
            const float* __restrict__ g2_w, const float* __restrict__ g2_b,
            const float* __restrict__ wq_w, const float* __restrict__ wq_b,
            const float* __restrict__ wk_w, const float* __restrict__ wk_b,
            const float* __restrict__ wv_w, const float* __restrict__ wv_b,
            const float* __restrict__ o_w,  const float* __restrict__ o_b,
            float* __restrict__ out)          // [B,H]
{
    const int b = blockIdx.x;
    const int tid = threadIdx.x;

    extern __shared__ float sm[];
    float* s_a   = sm;                    // [64][SA]
    float* s_t   = s_a + 64 * SA;         // [64][SA]
    float* s_adj = s_t + 64 * SA;         // [64][64]
    float* s_w   = s_adj + 64 * 64;       // [128][SH]
    float* s_b   = s_w + 128 * SH;        // [128]
    float* s_q   = s_b + 128;             // [128]
    float* s_cb  = s_q + 128;             // [128]
    float* s_wc  = s_cb + 128;            // [128]
    float* s_e   = s_wc + 128;            // [64]
    float* s_red = s_e + 64;              // [1]

    const float* htb = ht + (size_t)b * II * HH;
    for (int l = tid; l < II * HH; l += 256) {
        int i = l >> 7, h = l & 127;
        s_a[i * SA + h] = htb[l];
    }
    for (int l = tid; l < II * II; l += 256) s_adj[l] = adj[l];
    __syncthreads();

    const int h = tid & 127;
    const int i0 = (tid >> 7) * 32;

    // hop 1: s_t = adj @ ht ; s_a = relu(g1(s_t))
    adjmm(s_adj, s_a, s_t, h, i0);
    __syncthreads();
    stage_w(g1_w, s_w, tid);
    if (tid < 128) s_b[tid] = g1_b[tid];
    __syncthreads();
    lin128(s_w, s_b, s_t, s_a, h, i0, true);
    __syncthreads();

    // hop 2: s_t = adj @ g ; s_a = relu(g2(s_t)) = ctx
    adjmm(s_adj, s_a, s_t, h, i0);
    __syncthreads();
    stage_w(g2_w, s_w, tid);
    if (tid < 128) s_b[tid] = g2_b[tid];
    __syncthreads();
    lin128(s_w, s_b, s_t, s_a, h, i0, true);
    __syncthreads();

    // q = wq * ctx[63] + bq
    stage_w(wq_w, s_w, tid);
    if (tid < 128) s_b[tid] = wq_b[tid];
    __syncthreads();
    if (tid < 128) {
        float a = 0.0f;
#pragma unroll 8
        for (int k = 0; k < 128; k++)
            a = fmaf(s_w[tid * SH + k], s_a[63 * SA + k], a);
        s_q[tid] = a + s_b[tid];
    }
    __syncthreads();

    // K = wk(ctx) into s_t
    stage_w(wk_w, s_w, tid);
    if (tid < 128) s_b[tid] = wk_b[tid];
    __syncthreads();
    lin128(s_w, s_b, s_a, s_t, h, i0, false);
    __syncthreads();

    // e[i] = K[i] . q
    if (tid < 64) {
        float a = 0.0f;
#pragma unroll 8
        for (int k = 0; k < 128; k++)
            a = fmaf(s_t[tid * SA + k], s_q[k], a);
        s_e[tid] = a;
    }
    __syncthreads();

    // softmax over 64
    if (tid == 0) {
        float m = s_e[0];
        for (int i = 1; i < 64; i++) m = fmaxf(m, s_e[i]);
        s_red[0] = m;
    }
    __syncthreads();
    if (tid < 64) s_e[tid] = __expf(s_e[tid] - s_red[0]);
    __syncthreads();
    if (tid == 0) {
        float s = 0.0f;
        for (int i = 0; i < 64; i++) s += s_e[i];
        s_red[0] = __fdividef(1.0f, s);
    }
    __syncthreads();
    if (tid < 64) s_e[tid] *= s_red[0];
    __syncthreads();

    // cbar[k] = sum_i a[i] * ctx[i][k]
    if (tid < 128) {
        float a = 0.0f;
#pragma unroll 8
        for (int i = 0; i < 64; i++)
            a = fmaf(s_e[i], s_a[i * SA + tid], a);
        s_cb[tid] = a;
    }
    __syncthreads();

    // wctx = wv * cbar + bv  (valid since sum(a)=1)
    stage_w(wv_w, s_w, tid);
    if (tid < 128) s_b[tid] = wv_b[tid];
    __syncthreads();
    if (tid < 128) {
        float a = 0.0f;
#pragma unroll 8
        for (int k = 0; k < 128; k++)
            a = fmaf(s_w[tid * SH + k], s_cb[k], a);
        s_wc[tid] = a + s_b[tid];
    }
    __syncthreads();

    // output = relu(out0 * wctx + b)
    stage_w(o_w, s_w, tid);
    if (tid < 128) s_b[tid] = o_b[tid];
    __syncthreads();
    if (tid < 128) {
        float a = 0.0f;
#pragma unroll 8
        for (int k = 0; k < 128; k++)
            a = fmaf(s_w[tid * SH + k], s_wc[k], a);
        out[(size_t)b * HH + tid] = fmaxf(a + s_b[tid], 0.0f);
    }
}

// ---------------------------------------------------------------------------
// launch
// ---------------------------------------------------------------------------
extern "C" void kernel_launch(void* const* d_in, const int* in_sizes, int n_in,
                              void* d_out, int out_size) {
    const float* x     = (const float*)d_in[0];
    const float* W_ih  = (const float*)d_in[1];
    const float* W_hh  = (const float*)d_in[2];
    const float* b_ih  = (const float*)d_in[3];
    const float* b_hh  = (const float*)d_in[4];
    const float* fp_w  = (const float*)d_in[5];
    const float* fp_b  = (const float*)d_in[6];
    const float* g1_w  = (const float*)d_in[7];
    const float* g1_b  = (const float*)d_in[8];
    const float* g2_w  = (const float*)d_in[9];
    const float* g2_b  = (const float*)d_in[10];
    const float* wq_w  = (const float*)d_in[11];
    const float* wq_b  = (const float*)d_in[12];
    const float* wk_w  = (const float*)d_in[13];
    const float* wk_b  = (const float*)d_in[14];
    const float* wv_w  = (const float*)d_in[15];
    const float* wv_b  = (const float*)d_in[16];
    const float* o_w   = (const float*)d_in[17];
    const float* o_b   = (const float*)d_in[18];
    const float* adj   = (const float*)d_in[19];

    float* out = (float*)d_out;            // [B,H] first (tuple order)
    float* ht  = out + BB * HH;            // [B,I,H] second

    const int gru_smem  = GRU_SMEM_FLOATS * 4;
    const int post_smem = POST_SMEM_FLOATS * 4;
    cudaFuncSetAttribute(gru_kernel,  cudaFuncAttributeMaxDynamicSharedMemorySize, gru_smem);
    cudaFuncSetAttribute(post_kernel, cudaFuncAttributeMaxDynamicSharedMemorySize, post_smem);

    gru_kernel<<<dim3(II, BB / 128), 256, gru_smem>>>(
        x, W_ih, W_hh, b_ih, b_hh, fp_w, fp_b, ht);

    post_kernel<<<BB, 256, post_smem>>>(
        ht, adj, g1_w, g1_b, g2_w, g2_b, wq_w, wq_b, wk_w, wk_b,
        wv_w, wv_b, o_w, o_b, out);
}

// round 3
// speedup vs baseline: 1.5148x; 1.5148x over previous
#include <cuda_runtime.h>
#include <cstdint>

#define BB 512
#define TT 64
#define II 64
#define HH 128
#define H3 384
#define SHH 132  // s_h row stride (conflict-free fragment loads)
#define SH 129
#define SA 129

// Fragment-packed tf32 hi/lo weights:
// g_w*[feat][ct=48][kt=16][lane=32][j=2] ; element = W_hh[f][ct*8+lane/4][kt*8+lane%4+4j]
__device__ float g_whi[(size_t)II * H3 * HH];
__device__ float g_wlo[(size_t)II * H3 * HH];
__device__ float g_fphi[HH * HH];
__device__ float g_fplo[HH * HH];

// ---------------------------------------------------------------------------
// helpers
// ---------------------------------------------------------------------------
__device__ __forceinline__ float fast_sigmoid(float v) {
    return __fdividef(1.0f, 1.0f + __expf(-v));
}
__device__ __forceinline__ float fast_tanh(float v) {
    return __fdividef(2.0f, 1.0f + __expf(-2.0f * v)) - 1.0f;
}

__device__ __forceinline__ void cvt2(float a, uint32_t& hi, uint32_t& lo) {
    asm("cvt.rna.tf32.f32 %0, %1;" : "=r"(hi) : "f"(a));
    float d = a - __uint_as_float(hi);
    asm("cvt.rna.tf32.f32 %0, %1;" : "=r"(lo) : "f"(d));
}

__device__ __forceinline__ void mma8(float* c, const uint32_t* a, uint32_t b0, uint32_t b1) {
    asm volatile(
        "mma.sync.aligned.m16n8k8.row.col.f32.tf32.tf32.f32 "
        "{%0,%1,%2,%3}, {%4,%5,%6,%7}, {%8,%9}, {%0,%1,%2,%3};"
        : "+f"(c[0]), "+f"(c[1]), "+f"(c[2]), "+f"(c[3])
        : "r"(a[0]), "r"(a[1]), "r"(a[2]), "r"(a[3]), "r"(b0), "r"(b1));
}

// cp.async a 64-col phase chunk (8192 floats hi + 8192 lo) into smem buffers
__device__ __forceinline__ void stage_frag(float* dh, float* dl,
                                           const float* sh, const float* sl, int tid) {
    uint32_t ah = (uint32_t)__cvta_generic_to_shared(dh);
    uint32_t al = (uint32_t)__cvta_generic_to_shared(dl);
#pragma unroll
    for (int i = 0; i < 8; i++) {
        int ch = tid + (i << 8);   // 0..2047
        asm volatile("cp.async.cg.shared.global [%0], [%1], 16;"
                     :: "r"(ah + ch * 16), "l"(sh + ch * 4));
        asm volatile("cp.async.cg.shared.global [%0], [%1], 16;"
                     :: "r"(al + ch * 16), "l"(sl + ch * 4));
    }
}

// C[128 x 64] += h[128 x 128] * Wphase^T with tf32 hi/lo split (3 MMAs)
__device__ __forceinline__ void mma_phase(const float* __restrict__ s_h,
                                          const float* __restrict__ bh,
                                          const float* __restrict__ bl,
                                          int wm0, int wn, int grp, int qk, int lane,
                                          float (&acc)[2][4][4]) {
#pragma unroll
    for (int mt = 0; mt < 2; mt++)
#pragma unroll
        for (int nt = 0; nt < 4; nt++)
#pragma unroll
            for (int q = 0; q < 4; q++) acc[mt][nt][q] = 0.0f;

#pragma unroll 4
    for (int kt = 0; kt < 16; kt++) {
        uint32_t ahi[2][4], alo[2][4];
#pragma unroll
        for (int mt = 0; mt < 2; mt++) {
            const float* hp = s_h + (wm0 + mt * 16 + grp) * SHH + kt * 8 + qk;
            cvt2(hp[0],           ahi[mt][0], alo[mt][0]);
            cvt2(hp[8 * SHH],     ahi[mt][1], alo[mt][1]);
            cvt2(hp[4],           ahi[mt][2], alo[mt][2]);
            cvt2(hp[8 * SHH + 4], ahi[mt][3], alo[mt][3]);
        }
#pragma unroll
        for (int nt = 0; nt < 4; nt++) {
            int ctl = wn * 4 + nt;
            int fo = (ctl * 16 + kt) * 32 + lane;
            float2 vh = ((const float2*)bh)[fo];
            float2 vl = ((const float2*)bl)[fo];
            uint32_t b0h = __float_as_uint(vh.x), b1h = __float_as_uint(vh.y);
            uint32_t b0l = __float_as_uint(vl.x), b1l = __float_as_uint(vl.y);
#pragma unroll
            for (int mt = 0; mt < 2; mt++) {
                mma8(acc[mt][nt], ahi[mt], b0h, b1h);
                mma8(acc[mt][nt], ahi[mt], b0l, b1l);
                mma8(acc[mt][nt], alo[mt], b0h, b1h);
            }
        }
    }
}

// ---------------------------------------------------------------------------
// precompute: split W_hh and fp_w into tf32 hi/lo fragment-packed arrays
// ---------------------------------------------------------------------------
extern "C" __global__ void split_kernel(const float* __restrict__ W_hh,
                                        const float* __restrict__ fp_w) {
    const size_t stride = (size_t)gridDim.x * blockDim.x;
    const size_t i0 = (size_t)blockIdx.x * blockDim.x + threadIdx.x;
    const size_t totW = (size_t)II * H3 * HH;
    for (size_t idx = i0; idx < totW; idx += stride) {
        int j = (int)(idx & 1);
        int lane = (int)((idx >> 1) & 31);
        int kt = (int)((idx >> 6) & 15);
        int ct = (int)((idx >> 10) % 48);
        int f = (int)(idx / 49152);
        int row = ct * 8 + (lane >> 2);
        int k = kt * 8 + (lane & 3) + 4 * j;
        float v = W_hh[((size_t)f * H3 + row) * HH + k];
        uint32_t hi, lo;
        asm("cvt.rna.tf32.f32 %0, %1;" : "=r"(hi) : "f"(v));
        float d = v - __uint_as_float(hi);
        asm("cvt.rna.tf32.f32 %0, %1;" : "=r"(lo) : "f"(d));
        g_whi[idx] = __uint_as_float(hi);
        g_wlo[idx] = __uint_as_float(lo);
    }
    for (size_t idx = i0; idx < (size_t)HH * HH; idx += stride) {
        int j = (int)(idx & 1);
        int lane = (int)((idx >> 1) & 31);
        int kt = (int)((idx >> 6) & 15);
        int ct = (int)(idx >> 10);
        int row = ct * 8 + (lane >> 2);
        int k = kt * 8 + (lane & 3) + 4 * j;
        float v = fp_w[row * HH + k];
        uint32_t hi, lo;
        asm("cvt.rna.tf32.f32 %0, %1;" : "=r"(hi) : "f"(v));
        float d = v - __uint_as_float(hi);
        asm("cvt.rna.tf32.f32 %0, %1;" : "=r"(lo) : "f"(d));
        g_fphi[idx] = __uint_as_float(hi);
        g_fplo[idx] = __uint_as_float(lo);
    }
}

// ---------------------------------------------------------------------------
// GRU kernel: grid (64 features, 4 b-chunks of 128), 256 threads, tf32 MMA
// ---------------------------------------------------------------------------
#define GRU_SMEM_FLOATS (128 * SHH + 4 * 8192 + 256 + 3 * 384 + 128)

extern "C" __global__ void __launch_bounds__(256, 1)
gru_kernel(const float* __restrict__ x,      // [B,T,I]
           const float* __restrict__ W_ih,   // [I,3H]
           const float* __restrict__ b_ih,   // [I,3H]
           const float* __restrict__ b_hh,   // [I,3H]
           const float* __restrict__ fp_b,   // [H]
           float* __restrict__ ht_out)       // [B,I,H]
{
    const int feat = blockIdx.x;
    const int b0 = blockIdx.y << 7;
    const int tid = threadIdx.x;
    const int lane = tid & 31;
    const int warp = tid >> 5;
    const int wm0 = (warp >> 1) * 32;
    const int wn  = warp & 1;
    const int wn0 = wn * 32;
    const int grp = lane >> 2;
    const int qk  = lane & 3;

    extern __shared__ float sm[];
    float* s_h   = sm;                       // [128*SHH]
    float* s_bh  = s_h + 128 * SHH;          // [2*8192] hi buffers
    float* s_bl  = s_bh + 2 * 8192;          // [2*8192] lo buffers
    float* s_x   = s_bl + 2 * 8192;          // [2*128]
    float* s_wih = s_x + 256;                // [384]
    float* s_bih = s_wih + 384;              // [384]
    float* s_bhh = s_bih + 384;              // [384]
    float* s_fpb = s_bhh + 384;              // [128]

    for (int l = tid; l < 128 * SHH; l += 256) s_h[l] = 0.0f;
    for (int l = tid; l < 384; l += 256) {
        s_wih[l] = W_ih[feat * H3 + l];
        s_bih[l] = b_ih[feat * H3 + l];
        s_bhh[l] = b_hh[feat * H3 + l];
    }
    if (tid < 128) {
        s_fpb[tid] = fp_b[tid];
        s_x[tid] = x[(size_t)(b0 + tid) * (TT * II) + feat];
    }

    const float* wbh = g_whi + (size_t)feat * 49152;
    const float* wbl = g_wlo + (size_t)feat * 49152;

    // prefetch phase0 (R half0, ct0=0)
    stage_frag(s_bh, s_bl, wbh, wbl, tid);
    asm volatile("cp.async.commit_group;" ::: "memory");

    float keep0[32], keep1[32];
    float acc[2][4][4];
    int buf = 0;

#define PHASE_PRE(NH, NL)                                                        \
    asm volatile("cp.async.wait_group 0;" ::: "memory");                         \
    __syncthreads();                                                             \
    stage_frag(s_bh + ((buf ^ 1) << 13), s_bl + ((buf ^ 1) << 13), (NH), (NL), tid); \
    asm volatile("cp.async.commit_group;" ::: "memory");

#define MMA_CUR()                                                                \
    mma_phase(s_h, s_bh + (buf << 13), s_bl + (buf << 13), wm0, wn, grp, qk, lane, acc)

#define EPILOGUE(TYP, HALF, GOFF, KP)                                            \
    {                                                                            \
    _Pragma("unroll")                                                            \
    for (int mt = 0; mt < 2; mt++)                                               \
    _Pragma("unroll")                                                            \
    for (int nt = 0; nt < 4; nt++)                                               \
    _Pragma("unroll")                                                            \
    for (int q = 0; q < 4; q++) {                                                \
        int e = mt * 16 + nt * 4 + q;                                            \
        int row = wm0 + mt * 16 + grp + 8 * (q >> 1);                            \
        int cl = wn0 + nt * 8 + qk * 2 + (q & 1);                                \
        int g = (GOFF) + cl;                                                     \
        float xr = sx[row];                                                      \
        float giv = xr * s_wih[g] + s_bih[g];                                    \
        float a = acc[mt][nt][q] + s_bhh[g];                                     \
        if ((TYP) == 0) {                                                        \
            KP[e] = fast_sigmoid(a + giv);                                       \
        } else if ((TYP) == 1) {                                                 \
            KP[e] = fast_tanh(giv + KP[e] * a);                                  \
        } else {                                                                 \
            float z = fast_sigmoid(a + giv);                                     \
            float ho = s_h[row * SHH + (HALF) * 64 + cl];                        \
            KP[e] = (1.0f - z) * KP[e] + z * ho;                                 \
        }                                                                        \
    }                                                                            \
    }

    for (int t = 0; t < TT; t++) {
        const float* sx = s_x + ((t & 1) << 7);

        // P0: R half0 (ct0=0); next N half0 (ct0=32)
        PHASE_PRE(wbh + 32 * 1024, wbl + 32 * 1024);
        if (tid < 128 && t + 1 < TT)
            s_x[(((t + 1) & 1) << 7) + tid] =
                x[(size_t)(b0 + tid) * (TT * II) + (t + 1) * II + feat];
        MMA_CUR();
        EPILOGUE(0, 0, 0, keep0);
        buf ^= 1;

        // P1: N half0 (32); next R half1 (8)
        PHASE_PRE(wbh + 8 * 1024, wbl + 8 * 1024);
        MMA_CUR();
        EPILOGUE(1, 0, 256, keep0);
        buf ^= 1;

        // P2: R half1 (8); next N half1 (40)
        PHASE_PRE(wbh + 40 * 1024, wbl + 40 * 1024);
        MMA_CUR();
        EPILOGUE(0, 1, 64, keep1);
        buf ^= 1;

        // P3: N half1 (40); next Z half0 (16)
        PHASE_PRE(wbh + 16 * 1024, wbl + 16 * 1024);
        MMA_CUR();
        EPILOGUE(1, 1, 320, keep1);
        buf ^= 1;

        // P4: Z half0 (16); next Z half1 (24)
        PHASE_PRE(wbh + 24 * 1024, wbl + 24 * 1024);
        MMA_CUR();
        EPILOGUE(2, 0, 128, keep0);
        buf ^= 1;

        // P5: Z half1 (24); next: t+1 P0 (ct0=0) or fp half0
        {
            const float* nh = (t == TT - 1) ? g_fphi : wbh;
            const float* nl = (t == TT - 1) ? g_fplo : wbl;
            PHASE_PRE(nh, nl);
        }
        MMA_CUR();
        EPILOGUE(2, 1, 192, keep1);
        buf ^= 1;

        // write back h_new (keep0 = cols 0..63, keep1 = cols 64..127)
        __syncthreads();
#pragma unroll
        for (int mt = 0; mt < 2; mt++)
#pragma unroll
            for (int nt = 0; nt < 4; nt++)
#pragma unroll
                for (int q = 0; q < 4; q++) {
                    int e = mt * 16 + nt * 4 + q;
                    int row = wm0 + mt * 16 + grp + 8 * (q >> 1);
                    int cl = wn0 + nt * 8 + qk * 2 + (q & 1);
                    s_h[row * SHH + cl] = keep0[e];
                    s_h[row * SHH + 64 + cl] = keep1[e];
                }
        // next iteration's PHASE_PRE syncthreads orders these writes vs reads
    }

    // ---- projection: ht = fp_w * h + fp_b ----
    // proj half0 (buf holds fp ct 0..7); prefetch half1
    PHASE_PRE(g_fphi + 8 * 1024, g_fplo + 8 * 1024);
    MMA_CUR();
#pragma unroll
    for (int mt = 0; mt < 2; mt++)
#pragma unroll
        for (int nt = 0; nt < 4; nt++)
#pragma unroll
            for (int q = 0; q < 4; q++) {
                int row = wm0 + mt * 16 + grp + 8 * (q >> 1);
                int cl = wn0 + nt * 8 + qk * 2 + (q & 1);
                float v = acc[mt][nt][q] + s_fpb[cl];
                ht_out[((size_t)(b0 + row) * II + feat) * HH + cl] = v;
            }
    buf ^= 1;

    // proj half1
    asm volatile("cp.async.wait_group 0;" ::: "memory");
    __syncthreads();
    MMA_CUR();
#pragma unroll
    for (int mt = 0; mt < 2; mt++)
#pragma unroll
        for (int nt = 0; nt < 4; nt++)
#pragma unroll
            for (int q = 0; q < 4; q++) {
                int row = wm0 + mt * 16 + grp + 8 * (q >> 1);
                int cl = wn0 + nt * 8 + qk * 2 + (q & 1);
                float v = acc[mt][nt][q] + s_fpb[64 + cl];
                ht_out[((size_t)(b0 + row) * II + feat) * HH + 64 + cl] = v;
            }
}

// ---------------------------------------------------------------------------
// post kernel helpers (fp32, unchanged from R1)
// ---------------------------------------------------------------------------
__device__ __forceinline__ void stage_w(const float* __restrict__ W,
                                        float* __restrict__ s_w, int tid) {
    const float4* src = (const float4*)W;
#pragma unroll
    for (int it = 0; it < 16; it++) {
        int l = tid + it * 256;
        int g = l >> 5;
        int k = (l & 31) << 2;
        float4 v = src[l];
        float* d = s_w + g * SH + k;
        d[0] = v.x; d[1] = v.y; d[2] = v.z; d[3] = v.w;
    }
}

#define POST_SMEM_FLOATS (64 * SA + 64 * SA + 64 * 64 + 128 * SH + 128 + 128 + 128 + 128 + 64 + 32)

__device__ __forceinline__ void adjmm(const float* __restrict__ s_adj,
                                      const float* __restrict__ src,
                                      float* __restrict__ dst, int h, int i0) {
    for (int m = 0; m < 32; m++) {
        int i = i0 + m;
        float a = 0.0f;
#pragma unroll 8
        for (int j = 0; j < 64; j++)
            a = fmaf(s_adj[i * 64 + j], src[j * SA + h], a);
        dst[i * SA + h] = a;
    }
}

__device__ __forceinline__ void lin128(const float* __restrict__ s_w,
                                       const float* __restrict__ s_b,
                                       const float* __restrict__ src,
                                       float* __restrict__ dst,
                                       int h, int i0, bool do_relu) {
    float acc[32];
#pragma unroll
    for (int m = 0; m < 32; m++) acc[m] = 0.0f;
    for (int k = 0; k < 128; k++) {
        float w = s_w[h * SH + k];
#pragma unroll 8
        for (int m = 0; m < 32; m++)
            acc[m] = fmaf(w, src[(i0 + m) * SA + k], acc[m]);
    }
    float bb = s_b[h];
#pragma unroll
    for (int m = 0; m < 32; m++) {
        float v = acc[m] + bb;
        dst[(i0 + m) * SA + h] = do_relu ? fmaxf(v, 0.0f) : v;
    }
}

extern "C" __global__ void __launch_bounds__(256, 1)
post_kernel(const float* __restrict__ ht,
            const float* __restrict__ adj,
            const float* __restrict__ g1_w, const float* __restrict__ g1_b,
            const float* __restrict__ g2_w, const float* __restrict__ g2_b,
            const float* __restrict__ wq_w, const float* __restrict__ wq_b,
            const float* __restrict__ wk_w, const float* __restrict__ wk_b,
            const float* __restrict__ wv_w, const float* __restrict__ wv_b,
            const float* __restrict__ o_w,  const float* __restrict__ o_b,
            float* __restrict__ out)
{
    const int b = blockIdx.x;
    const int tid = threadIdx.x;

    extern __shared__ float sm[];
    float* s_a   = sm;
    float* s_t   = s_a + 64 * SA;
    float* s_adj = s_t + 64 * SA;
    float* s_w   = s_adj + 64 * 64;
    float* s_b   = s_w + 128 * SH;
    float* s_q   = s_b + 128;
    float* s_cb  = s_q + 128;
    float* s_wc  = s_cb + 128;
    float* s_e   = s_wc + 128;
    float* s_red = s_e + 64;

    const float* htb = ht + (size_t)b * II * HH;
    for (int l = tid; l < II * HH; l += 256) {
        int i = l >> 7, h = l & 127;
        s_a[i * SA + h] = htb[l];
    }
    for (int l = tid; l < II * II; l += 256) s_adj[l] = adj[l];
    __syncthreads();

    const int h = tid & 127;
    const int i0 = (tid >> 7) * 32;

    adjmm(s_adj, s_a, s_t, h, i0);
    __syncthreads();
    stage_w(g1_w, s_w, tid);
    if (tid < 128) s_b[tid] = g1_b[tid];
    __syncthreads();
    lin128(s_w, s_b, s_t, s_a, h, i0, true);
    __syncthreads();

    adjmm(s_adj, s_a, s_t, h, i0);
    __syncthreads();
    stage_w(g2_w, s_w, tid);
    if (tid < 128) s_b[tid] = g2_b[tid];
    __syncthreads();
    lin128(s_w, s_b, s_t, s_a, h, i0, true);
    __syncthreads();

    stage_w(wq_w, s_w, tid);
    if (tid < 128) s_b[tid] = wq_b[tid];
    __syncthreads();
    if (tid < 128) {
        float a = 0.0f;
#pragma unroll 8
        for (int k = 0; k < 128; k++)
            a = fmaf(s_w[tid * SH + k], s_a[63 * SA + k], a);
        s_q[tid] = a + s_b[tid];
    }
    __syncthreads();

    stage_w(wk_w, s_w, tid);
    if (tid < 128) s_b[tid] = wk_b[tid];
    __syncthreads();
    lin128(s_w, s_b, s_a, s_t, h, i0, false);
    __syncthreads();

    if (tid < 64) {
        float a = 0.0f;
#pragma unroll 8
        for (int k = 0; k < 128; k++)
            a = fmaf(s_t[tid * SA + k], s_q[k], a);
        s_e[tid] = a;
    }
    __syncthreads();

    if (tid == 0) {
        float m = s_e[0];
        for (int i = 1; i < 64; i++) m = fmaxf(m, s_e[i]);
        s_red[0] = m;
    }
    __syncthreads();
    if (tid < 64) s_e[tid] = __expf(s_e[tid] - s_red[0]);
    __syncthreads();
    if (tid == 0) {
        float s = 0.0f;
        for (int i = 0; i < 64; i++) s += s_e[i];
        s_red[0] = __fdividef(1.0f, s);
    }
    __syncthreads();
    if (tid < 64) s_e[tid] *= s_red[0];
    __syncthreads();

    if (tid < 128) {
        float a = 0.0f;
#pragma unroll 8
        for (int i = 0; i < 64; i++)
            a = fmaf(s_e[i], s_a[i * SA + tid], a);
        s_cb[tid] = a;
    }
    __syncthreads();

    stage_w(wv_w, s_w, tid);
    if (tid < 128) s_b[tid] = wv_b[tid];
    __syncthreads();
    if (tid < 128) {
        float a = 0.0f;
#pragma unroll 8
        for (int k = 0; k < 128; k++)
            a = fmaf(s_w[tid * SH + k], s_cb[k], a);
        s_wc[tid] = a + s_b[tid];
    }
    __syncthreads();

    stage_w(o_w, s_w, tid);
    if (tid < 128) s_b[tid] = o_b[tid];
    __syncthreads();
    if (tid < 128) {
        float a = 0.0f;
#pragma unroll 8
        for (int k = 0; k < 128; k++)
            a = fmaf(s_w[tid * SH + k], s_wc[k], a);
        out[(size_t)b * HH + tid] = fmaxf(a + s_b[tid], 0.0f);
    }
}

// ---------------------------------------------------------------------------
// launch
// ---------------------------------------------------------------------------
extern "C" void kernel_launch(void* const* d_in, const int* in_sizes, int n_in,
                              void* d_out, int out_size) {
    const float* x     = (const float*)d_in[0];
    const float* W_ih  = (const float*)d_in[1];
    const float* W_hh  = (const float*)d_in[2];
    const float* b_ih  = (const float*)d_in[3];
    const float* b_hh  = (const float*)d_in[4];
    const float* fp_w  = (const float*)d_in[5];
    const float* fp_b  = (const float*)d_in[6];
    const float* g1_w  = (const float*)d_in[7];
    const float* g1_b  = (const float*)d_in[8];
    const float* g2_w  = (const float*)d_in[9];
    const float* g2_b  = (const float*)d_in[10];
    const float* wq_w  = (const float*)d_in[11];
    const float* wq_b  = (const float*)d_in[12];
    const float* wk_w  = (const float*)d_in[13];
    const float* wk_b  = (const float*)d_in[14];
    const float* wv_w  = (const float*)d_in[15];
    const float* wv_b  = (const float*)d_in[16];
    const float* o_w   = (const float*)d_in[17];
    const float* o_b   = (const float*)d_in[18];
    const float* adj   = (const float*)d_in[19];

    float* out = (float*)d_out;            // [B,H] first (tuple order)
    float* ht  = out + BB * HH;            // [B,I,H] second

    const int gru_smem  = GRU_SMEM_FLOATS * 4;
    const int post_smem = POST_SMEM_FLOATS * 4;
    cudaFuncSetAttribute(gru_kernel,  cudaFuncAttributeMaxDynamicSharedMemorySize, gru_smem);
    cudaFuncSetAttribute(post_kernel, cudaFuncAttributeMaxDynamicSharedMemorySize, post_smem);

    split_kernel<<<2048, 256>>>(W_hh, fp_w);

    gru_kernel<<<dim3(II, BB / 128), 256, gru_smem>>>(
        x, W_ih, b_ih, b_hh, fp_b, ht);

    post_kernel<<<BB, 256, post_smem>>>(
        ht, adj, g1_w, g1_b, g2_w, g2_b, wq_w, wq_b, wk_w, wk_b,
        wv_w, wv_b, o_w, o_b, out);
}

// round 4
// speedup vs baseline: 1.5221x; 1.0048x over previous
#include <cuda_runtime.h>
#include <cuda_bf16.h>
#include <cstdint>

#define BB 512
#define TT 64
#define II 64
#define HH 128
#define H3 384
#define SH 129
#define SA 129
#define HKT 33   // packed-h row stride in uint2 units (conflict-free)

// Fragment-packed bf16 hi/lo weights.
// Per feature: [ct=48][kt=8][lane=32] -> uint4 {hi_b0, hi_b1, lo_b0, lo_b1}
// element(g = ct*8+lane/4, k = kt*16 + 2*(lane%4) + {0,1,8,9})
__device__ uint4 g_wpk[(size_t)II * 48 * 8 * 32];
__device__ uint4 g_fpk[16 * 8 * 32];

// ---------------------------------------------------------------------------
// helpers
// ---------------------------------------------------------------------------
__device__ __forceinline__ float fast_sigmoid(float v) {
    return __fdividef(1.0f, 1.0f + __expf(-v));
}
__device__ __forceinline__ float fast_tanh(float v) {
    return __fdividef(2.0f, 1.0f + __expf(-2.0f * v)) - 1.0f;
}
__device__ __forceinline__ uint32_t pk2(float a, float b) {
    __nv_bfloat162 t = __floats2bfloat162_rn(a, b);  // x=a (low), y=b (high)
    return *reinterpret_cast<uint32_t*>(&t);
}
__device__ __forceinline__ float bflo(uint32_t u) { return __uint_as_float(u << 16); }
__device__ __forceinline__ float bfhi(uint32_t u) { return __uint_as_float(u & 0xffff0000u); }

__device__ __forceinline__ void mma_bf16(float* c, const uint32_t* a,
                                         uint32_t b0, uint32_t b1) {
    asm volatile(
        "mma.sync.aligned.m16n8k16.row.col.f32.bf16.bf16.f32 "
        "{%0,%1,%2,%3}, {%4,%5,%6,%7}, {%8,%9}, {%0,%1,%2,%3};"
        : "+f"(c[0]), "+f"(c[1]), "+f"(c[2]), "+f"(c[3])
        : "r"(a[0]), "r"(a[1]), "r"(a[2]), "r"(a[3]), "r"(b0), "r"(b1));
}

// ---- mbarrier / bulk-copy primitives ----
__device__ __forceinline__ void mbar_init(uint32_t a, uint32_t cnt) {
    asm volatile("mbarrier.init.shared.b64 [%0], %1;" :: "r"(a), "r"(cnt) : "memory");
}
__device__ __forceinline__ void mbar_extx(uint32_t a, uint32_t tx) {
    asm volatile("mbarrier.arrive.expect_tx.shared.b64 _, [%0], %1;"
                 :: "r"(a), "r"(tx) : "memory");
}
__device__ __forceinline__ void mbar_wait(uint32_t a, uint32_t par) {
    asm volatile(
        "{\n\t.reg .pred P;\n"
        "WL%=:\n\t"
        "mbarrier.try_wait.parity.acquire.cta.shared::cta.b64 P, [%0], %1;\n\t"
        "@P bra WD%=;\n\t"
        "bra WL%=;\n"
        "WD%=:\n\t}"
        :: "r"(a), "r"(par) : "memory");
}
__device__ __forceinline__ void bulk_g2s(uint32_t dst, const void* src,
                                         uint32_t bytes, uint32_t mbar) {
    asm volatile(
        "cp.async.bulk.shared::cta.global.mbarrier::complete_tx::bytes "
        "[%0], [%1], %2, [%3];"
        :: "r"(dst), "l"(src), "r"(bytes), "r"(mbar) : "memory");
}

// ---------------------------------------------------------------------------
// split kernel: pack W_hh / fp_w into bf16 hi/lo fragment layout
// ---------------------------------------------------------------------------
extern "C" __global__ void split_kernel(const float* __restrict__ W_hh,
                                        const float* __restrict__ fp_w) {
    const size_t stride = (size_t)gridDim.x * blockDim.x;
    const size_t i0 = (size_t)blockIdx.x * blockDim.x + threadIdx.x;

    for (size_t idx = i0; idx < (size_t)II * 12288; idx += stride) {
        int lane = (int)(idx & 31);
        int kt = (int)((idx >> 5) & 7);
        int ct = (int)((idx >> 8) % 48);
        int f = (int)(idx / 12288);
        int g = ct * 8 + (lane >> 2);
        int k0 = kt * 16 + 2 * (lane & 3);
        const float* wr = W_hh + ((size_t)f * H3 + g) * HH + k0;
        float e0 = wr[0], e1 = wr[1], e2 = wr[8], e3 = wr[9];
        uint32_t hx = pk2(e0, e1), hy = pk2(e2, e3);
        uint32_t lx = pk2(e0 - bflo(hx), e1 - bfhi(hx));
        uint32_t ly = pk2(e2 - bflo(hy), e3 - bfhi(hy));
        g_wpk[idx] = make_uint4(hx, hy, lx, ly);
    }
    for (size_t idx = i0; idx < 4096; idx += stride) {
        int lane = (int)(idx & 31);
        int kt = (int)((idx >> 5) & 7);
        int ct = (int)(idx >> 8);  // 0..15
        int g = ct * 8 + (lane >> 2);
        int k0 = kt * 16 + 2 * (lane & 3);
        const float* wr = fp_w + g * HH + k0;
        float e0 = wr[0], e1 = wr[1], e2 = wr[8], e3 = wr[9];
        uint32_t hx = pk2(e0, e1), hy = pk2(e2, e3);
        uint32_t lx = pk2(e0 - bflo(hx), e1 - bfhi(hx));
        uint32_t ly = pk2(e2 - bflo(hy), e3 - bfhi(hy));
        g_fpk[idx] = make_uint4(hx, hy, lx, ly);
    }
}

// ---------------------------------------------------------------------------
// MMA phase: C[128x64] = h[128x128] * Wphase^T (bf16 3-term hi/lo)
// ---------------------------------------------------------------------------
__device__ __forceinline__ void mma_phase(const uint2* __restrict__ s_hh,
                                          const uint2* __restrict__ s_hl,
                                          const uint4* __restrict__ sb,
                                          int wm0, int wn, int grp, int qk, int lane,
                                          float (&acc)[2][4][4]) {
#pragma unroll
    for (int mt = 0; mt < 2; mt++)
#pragma unroll
        for (int nt = 0; nt < 4; nt++)
#pragma unroll
            for (int q = 0; q < 4; q++) acc[mt][nt][q] = 0.0f;

#pragma unroll
    for (int kt = 0; kt < 8; kt++) {
        uint32_t ah[2][4], al[2][4];
#pragma unroll
        for (int mt = 0; mt < 2; mt++) {
            int r0 = wm0 + mt * 16 + grp;
            uint2 h0 = s_hh[r0 * HKT + kt * 4 + qk];
            uint2 h1 = s_hh[(r0 + 8) * HKT + kt * 4 + qk];
            uint2 l0 = s_hl[r0 * HKT + kt * 4 + qk];
            uint2 l1 = s_hl[(r0 + 8) * HKT + kt * 4 + qk];
            ah[mt][0] = h0.x; ah[mt][1] = h1.x; ah[mt][2] = h0.y; ah[mt][3] = h1.y;
            al[mt][0] = l0.x; al[mt][1] = l1.x; al[mt][2] = l0.y; al[mt][3] = l1.y;
        }
#pragma unroll
        for (int nt = 0; nt < 4; nt++) {
            uint4 bv = sb[((wn * 4 + nt) * 8 + kt) * 32 + lane];
#pragma unroll
            for (int mt = 0; mt < 2; mt++) {
                mma_bf16(acc[mt][nt], ah[mt], bv.x, bv.y);   // hi*hi
                mma_bf16(acc[mt][nt], ah[mt], bv.z, bv.w);   // hi*lo
                mma_bf16(acc[mt][nt], al[mt], bv.x, bv.y);   // lo*hi
            }
        }
    }
}

// ---------------------------------------------------------------------------
// epilogues
// ---------------------------------------------------------------------------
__device__ __forceinline__ void epi_gate(bool is_tanh, float (&acc)[2][4][4],
                                         float* kp, int GOFF, const float* sx,
                                         int wm0, int wn0, int grp, int qk,
                                         const float* s_wih, const float* s_bih,
                                         const float* s_bhh) {
#pragma unroll
    for (int mt = 0; mt < 2; mt++)
#pragma unroll
        for (int q = 0; q < 4; q++) {
            int row = wm0 + mt * 16 + grp + 8 * (q >> 1);
            float xr = sx[row];
#pragma unroll
            for (int nt = 0; nt < 4; nt++) {
                int e = mt * 16 + nt * 4 + q;
                int cl = wn0 + nt * 8 + qk * 2 + (q & 1);
                int g = GOFF + cl;
                float giv = xr * s_wih[g] + s_bih[g];
                float a = acc[mt][nt][q] + s_bhh[g];
                kp[e] = is_tanh ? fast_tanh(giv + kp[e] * a)
                                : fast_sigmoid(a + giv);
            }
        }
}

__device__ __forceinline__ void epi_z(float (&acc)[2][4][4], float* kp, int half,
                                      const float* sx, int wm0, int wn0, int grp,
                                      int qk, const float* s_wih, const float* s_bih,
                                      const float* s_bhh,
                                      const uint2* __restrict__ s_hh,
                                      const uint2* __restrict__ s_hl) {
    const int GOFF = 128 + half * 64;
#pragma unroll
    for (int mt = 0; mt < 2; mt++)
#pragma unroll
        for (int rq = 0; rq < 2; rq++) {
            int row = wm0 + mt * 16 + grp + 8 * rq;
            float xr = sx[row];
#pragma unroll
            for (int ktp = 0; ktp < 2; ktp++) {
                int kt_s = half * 4 + (wn0 >> 4) + ktp;
                uint2 hv = s_hh[row * HKT + kt_s * 4 + qk];
                uint2 lv = s_hl[row * HKT + kt_s * 4 + qk];
#pragma unroll
                for (int ntl = 0; ntl < 2; ntl++) {
                    uint32_t hw = ntl ? hv.y : hv.x;
                    uint32_t lw = ntl ? lv.y : lv.x;
#pragma unroll
                    for (int b = 0; b < 2; b++) {
                        int nt = ktp * 2 + ntl;
                        int e = mt * 16 + nt * 4 + rq * 2 + b;
                        int cl = wn0 + nt * 8 + qk * 2 + b;
                        int g = GOFF + cl;
                        float hold = (b ? bfhi(hw) : bflo(hw)) +
                                     (b ? bfhi(lw) : bflo(lw));
                        float z = fast_sigmoid(acc[mt][nt][rq * 2 + b] + s_bhh[g] +
                                               xr * s_wih[g] + s_bih[g]);
                        kp[e] = (1.0f - z) * kp[e] + z * hold;
                    }
                }
            }
        }
}

__device__ __forceinline__ void write_h(uint2* s_hh, uint2* s_hl,
                                        const float* k0, const float* k1,
                                        int wm0, int wn0, int grp, int qk) {
#pragma unroll
    for (int mt = 0; mt < 2; mt++)
#pragma unroll
        for (int rq = 0; rq < 2; rq++) {
            int row = wm0 + mt * 16 + grp + 8 * rq;
#pragma unroll
            for (int half = 0; half < 2; half++) {
                const float* kp = half ? k1 : k0;
#pragma unroll
                for (int ktp = 0; ktp < 2; ktp++) {
                    int kt_s = half * 4 + (wn0 >> 4) + ktp;
                    float v00 = kp[mt * 16 + (ktp * 2 + 0) * 4 + rq * 2 + 0];
                    float v01 = kp[mt * 16 + (ktp * 2 + 0) * 4 + rq * 2 + 1];
                    float v10 = kp[mt * 16 + (ktp * 2 + 1) * 4 + rq * 2 + 0];
                    float v11 = kp[mt * 16 + (ktp * 2 + 1) * 4 + rq * 2 + 1];
                    uint32_t hx = pk2(v00, v01);
                    uint32_t hy = pk2(v10, v11);
                    uint32_t lx = pk2(v00 - bflo(hx), v01 - bfhi(hx));
                    uint32_t ly = pk2(v10 - bflo(hy), v11 - bfhi(hy));
                    s_hh[row * HKT + kt_s * 4 + qk] = make_uint2(hx, hy);
                    s_hl[row * HKT + kt_s * 4 + qk] = make_uint2(lx, ly);
                }
            }
        }
}

// ---------------------------------------------------------------------------
// GRU kernel
// ---------------------------------------------------------------------------
// smem layout (bytes):
//   0        s_b   uint4[2][2048]   65536
//   65536    s_hh  uint2[128*33]    33792
//   99328    s_hl  uint2[128*33]    33792
//   133120   s_x   float[2*128]     1024
//   134144   s_wih float[384]       1536
//   135680   s_bih float[384]       1536
//   137216   s_bhh float[384]       1536
//   138752   s_fpb float[128]       512
//   139264   mbar  u64[2]           16
#define GRU_SMEM_BYTES 139280

extern "C" __global__ void __launch_bounds__(256, 1)
gru_kernel(const float* __restrict__ x,      // [B,T,I]
           const float* __restrict__ W_ih,   // [I,3H]
           const float* __restrict__ b_ih,   // [I,3H]
           const float* __restrict__ b_hh,   // [I,3H]
           const float* __restrict__ fp_b,   // [H]
           float* __restrict__ ht_out)       // [B,I,H]
{
    const int feat = blockIdx.x;
    const int b0 = blockIdx.y << 7;
    const int tid = threadIdx.x;
    const int lane = tid & 31;
    const int warp = tid >> 5;
    const int wm0 = (warp >> 1) * 32;
    const int wn  = warp & 1;
    const int wn0 = wn * 32;
    const int grp = lane >> 2;
    const int qk  = lane & 3;

    extern __shared__ char smraw[];
    uint4* s_b   = (uint4*)smraw;                       // [2][2048]
    uint2* s_hh  = (uint2*)(smraw + 65536);
    uint2* s_hl  = (uint2*)(smraw + 99328);
    float* s_x   = (float*)(smraw + 133120);
    float* s_wih = (float*)(smraw + 134144);
    float* s_bih = (float*)(smraw + 135680);
    float* s_bhh = (float*)(smraw + 137216);
    float* s_fpb = (float*)(smraw + 138752);
    uint32_t mb0 = (uint32_t)__cvta_generic_to_shared(smraw + 139264);
    uint32_t mb1 = mb0 + 8;
    uint32_t sb0 = (uint32_t)__cvta_generic_to_shared(s_b);
    uint32_t sb1 = sb0 + 32768;

    // init
    {
        uint4 z4 = make_uint4(0, 0, 0, 0);
        uint4* hz = (uint4*)s_hh;   // s_hh + s_hl contiguous: 67584 B = 4224 uint4
        for (int l = tid; l < 4224; l += 256) hz[l] = z4;
    }
    for (int l = tid; l < 384; l += 256) {
        s_wih[l] = W_ih[feat * H3 + l];
        s_bih[l] = b_ih[feat * H3 + l];
        s_bhh[l] = b_hh[feat * H3 + l];
    }
    if (tid < 128) {
        s_fpb[tid] = fp_b[tid];
        s_x[tid] = x[(size_t)(b0 + tid) * (TT * II) + feat];
    }
    if (tid == 0) { mbar_init(mb0, 1); mbar_init(mb1, 1); }
    asm volatile("fence.proxy.async.shared::cta;" ::: "memory");
    __syncthreads();

    const char* wsrc = (const char*)(g_wpk + (size_t)feat * 12288);
    // phase byte offsets: R0, N0, R1, N1, Z0, Z1
    // ct0:               0,  32,  8,  40, 16, 24

    int phs0 = 0, phs1 = 0;

    if (tid == 0) { mbar_extx(mb0, 32768u); bulk_g2s(sb0, wsrc + 0, 32768u, mb0); }

    float keep0[32], keep1[32];
    float acc[2][4][4];

#define PRE0(SRC)  /* wait buf0, issue SRC -> buf1 */                            \
    mbar_wait(mb0, phs0); phs0 ^= 1;                                             \
    __syncthreads();                                                             \
    if (tid == 0) { mbar_extx(mb1, 32768u); bulk_g2s(sb1, (SRC), 32768u, mb1); }

#define PRE1(SRC)  /* wait buf1, issue SRC -> buf0 */                            \
    mbar_wait(mb1, phs1); phs1 ^= 1;                                             \
    __syncthreads();                                                             \
    if (tid == 0) { mbar_extx(mb0, 32768u); bulk_g2s(sb0, (SRC), 32768u, mb0); }

    for (int t = 0; t < TT; t++) {
        const float* sx = s_x + ((t & 1) << 7);

        // P0: R half0 (buf0) ; prefetch N half0
        PRE0(wsrc + 131072);
        if (tid < 128 && t + 1 < TT)
            s_x[(((t + 1) & 1) << 7) + tid] =
                x[(size_t)(b0 + tid) * (TT * II) + (t + 1) * II + feat];
        mma_phase(s_hh, s_hl, s_b, wm0, wn, grp, qk, lane, acc);
        epi_gate(false, acc, keep0, 0, sx, wm0, wn0, grp, qk, s_wih, s_bih, s_bhh);

        // P1: N half0 (buf1) ; prefetch R half1
        PRE1(wsrc + 32768);
        mma_phase(s_hh, s_hl, s_b + 2048, wm0, wn, grp, qk, lane, acc);
        epi_gate(true, acc, keep0, 256, sx, wm0, wn0, grp, qk, s_wih, s_bih, s_bhh);

        // P2: R half1 (buf0) ; prefetch N half1
        PRE0(wsrc + 163840);
        mma_phase(s_hh, s_hl, s_b, wm0, wn, grp, qk, lane, acc);
        epi_gate(false, acc, keep1, 64, sx, wm0, wn0, grp, qk, s_wih, s_bih, s_bhh);

        // P3: N half1 (buf1) ; prefetch Z half0
        PRE1(wsrc + 65536);
        mma_phase(s_hh, s_hl, s_b + 2048, wm0, wn, grp, qk, lane, acc);
        epi_gate(true, acc, keep1, 320, sx, wm0, wn0, grp, qk, s_wih, s_bih, s_bhh);

        // P4: Z half0 (buf0) ; prefetch Z half1
        PRE0(wsrc + 98304);
        mma_phase(s_hh, s_hl, s_b, wm0, wn, grp, qk, lane, acc);
        epi_z(acc, keep0, 0, sx, wm0, wn0, grp, qk, s_wih, s_bih, s_bhh, s_hh, s_hl);

        // P5: Z half1 (buf1) ; prefetch next (t+1 R0, or fp half0)
        {
            const char* nxt = (t + 1 < TT) ? wsrc : (const char*)g_fpk;
            PRE1(nxt);
        }
        mma_phase(s_hh, s_hl, s_b + 2048, wm0, wn, grp, qk, lane, acc);
        epi_z(acc, keep1, 1, sx, wm0, wn0, grp, qk, s_wih, s_bih, s_bhh, s_hh, s_hl);

        // h writeback (packed bf16 hi/lo, A-fragment layout)
        __syncthreads();
        write_h(s_hh, s_hl, keep0, keep1, wm0, wn0, grp, qk);
        // next PRE's __syncthreads orders these writes before reads
    }

    // ---- projection: ht = fp_w * h + fp_b ----
    // proj half0 (buf0), prefetch fp half1
    PRE0((const char*)g_fpk + 32768);
    mma_phase(s_hh, s_hl, s_b, wm0, wn, grp, qk, lane, acc);
#pragma unroll
    for (int mt = 0; mt < 2; mt++)
#pragma unroll
        for (int q2 = 0; q2 < 2; q2++) {
            int row = wm0 + mt * 16 + grp + 8 * q2;
            size_t base = ((size_t)(b0 + row) * II + feat) * HH;
#pragma unroll
            for (int nt = 0; nt < 4; nt++) {
                int cl = wn0 + nt * 8 + qk * 2;
                float2 v = make_float2(acc[mt][nt][q2 * 2] + s_fpb[cl],
                                       acc[mt][nt][q2 * 2 + 1] + s_fpb[cl + 1]);
                *(float2*)(ht_out + base + cl) = v;
            }
        }

    // proj half1 (buf1)
    mbar_wait(mb1, phs1);
    mma_phase(s_hh, s_hl, s_b + 2048, wm0, wn, grp, qk, lane, acc);
#pragma unroll
    for (int mt = 0; mt < 2; mt++)
#pragma unroll
        for (int q2 = 0; q2 < 2; q2++) {
            int row = wm0 + mt * 16 + grp + 8 * q2;
            size_t base = ((size_t)(b0 + row) * II + feat) * HH + 64;
#pragma unroll
            for (int nt = 0; nt < 4; nt++) {
                int cl = wn0 + nt * 8 + qk * 2;
                float2 v = make_float2(acc[mt][nt][q2 * 2] + s_fpb[64 + cl],
                                       acc[mt][nt][q2 * 2 + 1] + s_fpb[64 + cl + 1]);
                *(float2*)(ht_out + base + cl) = v;
            }
        }
#undef PRE0
#undef PRE1
}

// ---------------------------------------------------------------------------
// post kernel (fp32, unchanged; ~1 us)
// ---------------------------------------------------------------------------
__device__ __forceinline__ void stage_w(const float* __restrict__ W,
                                        float* __restrict__ s_w, int tid) {
    const float4* src = (const float4*)W;
#pragma unroll
    for (int it = 0; it < 16; it++) {
        int l = tid + it * 256;
        int g = l >> 5;
        int k = (l & 31) << 2;
        float4 v = src[l];
        float* d = s_w + g * SH + k;
        d[0] = v.x; d[1] = v.y; d[2] = v.z; d[3] = v.w;
    }
}

#define POST_SMEM_FLOATS (64 * SA + 64 * SA + 64 * 64 + 128 * SH + 128 + 128 + 128 + 128 + 64 + 32)

__device__ __forceinline__ void adjmm(const float* __restrict__ s_adj,
                                      const float* __restrict__ src,
                                      float* __restrict__ dst, int h, int i0) {
    for (int m = 0; m < 32; m++) {
        int i = i0 + m;
        float a = 0.0f;
#pragma unroll 8
        for (int j = 0; j < 64; j++)
            a = fmaf(s_adj[i * 64 + j], src[j * SA + h], a);
        dst[i * SA + h] = a;
    }
}

__device__ __forceinline__ void lin128(const float* __restrict__ s_w,
                                       const float* __restrict__ s_b,
                                       const float* __restrict__ src,
                                       float* __restrict__ dst,
                                       int h, int i0, bool do_relu) {
    float acc[32];
#pragma unroll
    for (int m = 0; m < 32; m++) acc[m] = 0.0f;
    for (int k = 0; k < 128; k++) {
        float w = s_w[h * SH + k];
#pragma unroll 8
        for (int m = 0; m < 32; m++)
            acc[m] = fmaf(w, src[(i0 + m) * SA + k], acc[m]);
    }
    float bb = s_b[h];
#pragma unroll
    for (int m = 0; m < 32; m++) {
        float v = acc[m] + bb;
        dst[(i0 + m) * SA + h] = do_relu ? fmaxf(v, 0.0f) : v;
    }
}

extern "C" __global__ void __launch_bounds__(256, 1)
post_kernel(const float* __restrict__ ht,
            const float* __restrict__ adj,
            const float* __restrict__ g1_w, const float* __restrict__ g1_b,
            const float* __restrict__ g2_w, const float* __restrict__ g2_b,
            const float* __restrict__ wq_w, const float* __restrict__ wq_b,
            const float* __restrict__ wk_w, const float* __restrict__ wk_b,
            const float* __restrict__ wv_w, const float* __restrict__ wv_b,
            const float* __restrict__ o_w,  const float* __restrict__ o_b,
            float* __restrict__ out)
{
    const int b = blockIdx.x;
    const int tid = threadIdx.x;

    extern __shared__ float sm[];
    float* s_a   = sm;
    float* s_t   = s_a + 64 * SA;
    float* s_adj = s_t + 64 * SA;
    float* s_w   = s_adj + 64 * 64;
    float* s_b   = s_w + 128 * SH;
    float* s_q   = s_b + 128;
    float* s_cb  = s_q + 128;
    float* s_wc  = s_cb + 128;
    float* s_e   = s_wc + 128;
    float* s_red = s_e + 64;

    const float* htb = ht + (size_t)b * II * HH;
    for (int l = tid; l < II * HH; l += 256) {
        int i = l >> 7, h = l & 127;
        s_a[i * SA + h] = htb[l];
    }
    for (int l = tid; l < II * II; l += 256) s_adj[l] = adj[l];
    __syncthreads();

    const int h = tid & 127;
    const int i0 = (tid >> 7) * 32;

    adjmm(s_adj, s_a, s_t, h, i0);
    __syncthreads();
    stage_w(g1_w, s_w, tid);
    if (tid < 128) s_b[tid] = g1_b[tid];
    __syncthreads();
    lin128(s_w, s_b, s_t, s_a, h, i0, true);
    __syncthreads();

    adjmm(s_adj, s_a, s_t, h, i0);
    __syncthreads();
    stage_w(g2_w, s_w, tid);
    if (tid < 128) s_b[tid] = g2_b[tid];
    __syncthreads();
    lin128(s_w, s_b, s_t, s_a, h, i0, true);
    __syncthreads();

    stage_w(wq_w, s_w, tid);
    if (tid < 128) s_b[tid] = wq_b[tid];
    __syncthreads();
    if (tid < 128) {
        float a = 0.0f;
#pragma unroll 8
        for (int k = 0; k < 128; k++)
            a = fmaf(s_w[tid * SH + k], s_a[63 * SA + k], a);
        s_q[tid] = a + s_b[tid];
    }
    __syncthreads();

    stage_w(wk_w, s_w, tid);
    if (tid < 128) s_b[tid] = wk_b[tid];
    __syncthreads();
    lin128(s_w, s_b, s_a, s_t, h, i0, false);
    __syncthreads();

    if (tid < 64) {
        float a = 0.0f;
#pragma unroll 8
        for (int k = 0; k < 128; k++)
            a = fmaf(s_t[tid * SA + k], s_q[k], a);
        s_e[tid] = a;
    }
    __syncthreads();

    if (tid == 0) {
        float m = s_e[0];
        for (int i = 1; i < 64; i++) m = fmaxf(m, s_e[i]);
        s_red[0] = m;
    }
    __syncthreads();
    if (tid < 64) s_e[tid] = __expf(s_e[tid] - s_red[0]);
    __syncthreads();
    if (tid == 0) {
        float s = 0.0f;
        for (int i = 0; i < 64; i++) s += s_e[i];
        s_red[0] = __fdividef(1.0f, s);
    }
    __syncthreads();
    if (tid < 64) s_e[tid] *= s_red[0];
    __syncthreads();

    if (tid < 128) {
        float a = 0.0f;
#pragma unroll 8
        for (int i = 0; i < 64; i++)
            a = fmaf(s_e[i], s_a[i * SA + tid], a);
        s_cb[tid] = a;
    }
    __syncthreads();

    stage_w(wv_w, s_w, tid);
    if (tid < 128) s_b[tid] = wv_b[tid];
    __syncthreads();
    if (tid < 128) {
        float a = 0.0f;
#pragma unroll 8
        for (int k = 0; k < 128; k++)
            a = fmaf(s_w[tid * SH + k], s_cb[k], a);
        s_wc[tid] = a + s_b[tid];
    }
    __syncthreads();

    stage_w(o_w, s_w, tid);
    if (tid < 128) s_b[tid] = o_b[tid];
    __syncthreads();
    if (tid < 128) {
        float a = 0.0f;
#pragma unroll 8
        for (int k = 0; k < 128; k++)
            a = fmaf(s_w[tid * SH + k], s_wc[k], a);
        out[(size_t)b * HH + tid] = fmaxf(a + s_b[tid], 0.0f);
    }
}

// ---------------------------------------------------------------------------
// launch
// ---------------------------------------------------------------------------
extern "C" void kernel_launch(void* const* d_in, const int* in_sizes, int n_in,
                              void* d_out, int out_size) {
    const float* x     = (const float*)d_in[0];
    const float* W_ih  = (const float*)d_in[1];
    const float* W_hh  = (const float*)d_in[2];
    const float* b_ih  = (const float*)d_in[3];
    const float* b_hh  = (const float*)d_in[4];
    const float* fp_w  = (const float*)d_in[5];
    const float* fp_b  = (const float*)d_in[6];
    const float* g1_w  = (const float*)d_in[7];
    const float* g1_b  = (const float*)d_in[8];
    const float* g2_w  = (const float*)d_in[9];
    const float* g2_b  = (const float*)d_in[10];
    const float* wq_w  = (const float*)d_in[11];
    const float* wq_b  = (const float*)d_in[12];
    const float* wk_w  = (const float*)d_in[13];
    const float* wk_b  = (const float*)d_in[14];
    const float* wv_w  = (const float*)d_in[15];
    const float* wv_b  = (const float*)d_in[16];
    const float* o_w   = (const float*)d_in[17];
    const float* o_b   = (const float*)d_in[18];
    const float* adj   = (const float*)d_in[19];

    float* out = (float*)d_out;            // [B,H] first (tuple order)
    float* ht  = out + BB * HH;            // [B,I,H] second

    const int post_smem = POST_SMEM_FLOATS * 4;
    cudaFuncSetAttribute(gru_kernel,  cudaFuncAttributeMaxDynamicSharedMemorySize, GRU_SMEM_BYTES);
    cudaFuncSetAttribute(post_kernel, cudaFuncAttributeMaxDynamicSharedMemorySize, post_smem);

    split_kernel<<<1024, 256>>>(W_hh, fp_w);

    gru_kernel<<<dim3(II, BB / 128), 256, GRU_SMEM_BYTES>>>(
        x, W_ih, b_ih, b_hh, fp_b, ht);

    post_kernel<<<BB, 256, post_smem>>>(
        ht, adj, g1_w, g1_b, g2_w, g2_b, wq_w, wq_b, wk_w, wk_b,
        wv_w, wv_b, o_w, o_b, out);
}